// round 3
// baseline (speedup 1.0000x reference)
#include <cuda_runtime.h>

// Problem constants
#define Bv   16
#define Nv   4096
#define Mv   1024
#define C1v  256
#define C2v  512
#define CIN  768           // C1 + C2
#define Hv   256
#define NPTS (Bv * Nv)     // 65536

// ---------------- scratch (device globals; no cudaMalloc allowed) ----------
static __device__ float g_kfT[(size_t)Bv * Mv * C2v];     // (B, M, C2) transposed known_feats
static __device__ float g_feats[(size_t)NPTS * CIN];      // (B*N, 768) concatenated features
static __device__ float g_y1[(size_t)NPTS * Hv];          // GEMM1 output
static __device__ float g_y2[(size_t)NPTS * Hv];          // GEMM2 output
static __device__ float g_wT1[CIN * Hv];                  // w1^T  (768 x 256)
static __device__ float g_wT2[Hv * Hv];                   // w2^T  (256 x 256)
static __device__ float g_psum[256 * Hv];
static __device__ float g_psq[256 * Hv];
static __device__ float g_sc1[Hv], g_sh1[Hv];
static __device__ float g_sc2[Hv], g_sh2[Hv];

// ---------------- generic tiled transpose ----------------------------------
// in: (rows x cols) per batch; out element (r=orig col, oc=orig row):
//   out[b*obs + r*old + ooff + oc] = in[b*ibs + oc*cols + r]
// DST selects the destination device-global buffer.
template <int DST>
__global__ void transpose_k(const float* __restrict__ in,
                            int rows, int cols,
                            long ibs, long obs, int old, int ooff) {
    float* out = (DST == 0) ? g_wT1 : (DST == 1) ? g_wT2 : (DST == 2) ? g_kfT : g_feats;
    __shared__ float t[32][33];
    const float* ib = in + (long)blockIdx.z * ibs;
    float* ob = out + (long)blockIdx.z * obs;

    int c = blockIdx.x * 32 + threadIdx.x;  // input col
    int r0 = blockIdx.y * 32;               // input row base
#pragma unroll
    for (int i = threadIdx.y; i < 32; i += 8) {
        int r = r0 + i;
        if (r < rows && c < cols) t[i][threadIdx.x] = ib[(long)r * cols + c];
    }
    __syncthreads();
    int oc = r0 + threadIdx.x;      // output col = original row
    int orow0 = blockIdx.x * 32;    // output row base = original col
#pragma unroll
    for (int i = threadIdx.y; i < 32; i += 8) {
        int r = orow0 + i;
        if (r < cols && oc < rows)
            ob[(long)r * old + ooff + oc] = t[threadIdx.x][i];
    }
}

// ---------------- 3-NN + inverse-distance interpolation --------------------
// grid: (B, N/256), 256 threads. Each thread owns one query point.
__global__ __launch_bounds__(256) void knn_interp_kernel(
    const float* __restrict__ unknown, const float* __restrict__ known) {
    __shared__ float4 kn[Mv];
    const int b = blockIdx.x;
    const int tid = threadIdx.x;

    const float* kb = known + (long)b * Mv * 3;
    for (int m = tid; m < Mv; m += 256) {
        float x = kb[m * 3 + 0], y = kb[m * 3 + 1], z = kb[m * 3 + 2];
        kn[m] = make_float4(x, y, z, x * x + y * y + z * z);
    }
    __syncthreads();

    const int n = blockIdx.y * 256 + tid;
    const float* up = unknown + ((long)b * Nv + n) * 3;
    float ux = up[0], uy = up[1], uz = up[2];
    float un2 = ux * ux + uy * uy + uz * uz;
    float ax = -2.f * ux, ay = -2.f * uy, az = -2.f * uz;

    float d0 = 1e30f, d1 = 1e30f, d2 = 1e30f;
    int i0 = 0, i1 = 0, i2 = 0;
#pragma unroll 4
    for (int m = 0; m < Mv; m++) {
        float4 p = kn[m];
        float d = fmaf(ax, p.x, fmaf(ay, p.y, fmaf(az, p.z, p.w)));
        if (d < d2) {
            if (d < d1) {
                d2 = d1; i2 = i1;
                if (d < d0) { d1 = d0; i1 = i0; d0 = d; i0 = m; }
                else        { d1 = d;  i1 = m; }
            } else { d2 = d; i2 = m; }
        }
    }
    d0 += un2; d1 += un2; d2 += un2;
    float w0 = 1.f / (d0 + 1e-8f);
    float w1 = 1.f / (d1 + 1e-8f);
    float w2 = 1.f / (d2 + 1e-8f);
    float ws = 1.f / (w0 + w1 + w2);
    w0 *= ws; w1 *= ws; w2 *= ws;

    const float4* r0 = (const float4*)(g_kfT + ((long)b * Mv + i0) * C2v);
    const float4* r1 = (const float4*)(g_kfT + ((long)b * Mv + i1) * C2v);
    const float4* r2 = (const float4*)(g_kfT + ((long)b * Mv + i2) * C2v);
    float4* outp = (float4*)(g_feats + ((long)b * Nv + n) * CIN + C1v);
#pragma unroll 4
    for (int c = 0; c < C2v / 4; c++) {
        float4 f0 = r0[c], f1 = r1[c], f2 = r2[c];
        float4 o;
        o.x = fmaf(w0, f0.x, fmaf(w1, f1.x, w2 * f2.x));
        o.y = fmaf(w0, f0.y, fmaf(w1, f1.y, w2 * f2.y));
        o.z = fmaf(w0, f0.z, fmaf(w1, f1.z, w2 * f2.z));
        o.w = fmaf(w0, f0.w, fmaf(w1, f1.w, w2 * f2.w));
        outp[c] = o;
    }
}

// ---------------- SGEMM: C(M x 256) = A(M x K) * W(K x 256) ----------------
// 128x128 tile, BK=16, 256 threads, 8x8 per thread.
// STAGE==1: A=g_feats (K=768) -> g_y1.
// STAGE==2: A=g_y1    (K=256) -> g_y2, with fused BN1+ReLU on the A load.
template <int STAGE>
__global__ __launch_bounds__(256) void sgemm_kernel() {
    constexpr int K = (STAGE == 1) ? CIN : Hv;
    const float* A = (STAGE == 1) ? g_feats : g_y1;
    const float* W = (STAGE == 1) ? g_wT1 : g_wT2;
    float* C = (STAGE == 1) ? g_y1 : g_y2;

    __shared__ float As[16][132];
    __shared__ float Bs[16][128];

    const int tid = threadIdx.x;
    const long m0 = (long)blockIdx.y * 128;
    const int n0 = blockIdx.x * 128;
    const float* Ab = A + m0 * K;
    const float* Wb = W + n0;

    const int arow = tid >> 2, ac4 = tid & 3;   // A tile: 128 rows x 4 float4
    const int brow = tid >> 5, bc4 = tid & 31;  // W tile: 16 rows x 32 float4
    const int tx = tid & 15, ty = tid >> 4;

    float acc[8][8];
#pragma unroll
    for (int i = 0; i < 8; i++)
#pragma unroll
        for (int j = 0; j < 8; j++) acc[i][j] = 0.f;

    for (int k0 = 0; k0 < K; k0 += 16) {
        // stage A (transposed into As[k][m])
#pragma unroll
        for (int h = 0; h < 2; h++) {
            int r = arow + h * 64;
            float4 v = *(const float4*)&Ab[(long)r * K + k0 + ac4 * 4];
            if (STAGE == 2) {
                int kg = k0 + ac4 * 4;
                v.x = fmaxf(fmaf(v.x, g_sc1[kg + 0], g_sh1[kg + 0]), 0.f);
                v.y = fmaxf(fmaf(v.y, g_sc1[kg + 1], g_sh1[kg + 1]), 0.f);
                v.z = fmaxf(fmaf(v.z, g_sc1[kg + 2], g_sh1[kg + 2]), 0.f);
                v.w = fmaxf(fmaf(v.w, g_sc1[kg + 3], g_sh1[kg + 3]), 0.f);
            }
            As[ac4 * 4 + 0][r] = v.x;
            As[ac4 * 4 + 1][r] = v.y;
            As[ac4 * 4 + 2][r] = v.z;
            As[ac4 * 4 + 3][r] = v.w;
        }
        // stage W (already K x 256, coalesced)
#pragma unroll
        for (int h = 0; h < 2; h++) {
            int r = brow + h * 8;
            *(float4*)&Bs[r][bc4 * 4] = *(const float4*)&Wb[(long)(k0 + r) * Hv + bc4 * 4];
        }
        __syncthreads();

#pragma unroll
        for (int kk = 0; kk < 16; kk++) {
            float4 a0 = *(const float4*)&As[kk][ty * 8];
            float4 a1 = *(const float4*)&As[kk][ty * 8 + 4];
            float4 b0 = *(const float4*)&Bs[kk][tx * 4];        // cols tx*4 .. tx*4+3
            float4 b1 = *(const float4*)&Bs[kk][64 + tx * 4];   // cols 64+tx*4 ..
            float av[8] = {a0.x, a0.y, a0.z, a0.w, a1.x, a1.y, a1.z, a1.w};
            float bv[8] = {b0.x, b0.y, b0.z, b0.w, b1.x, b1.y, b1.z, b1.w};
#pragma unroll
            for (int i = 0; i < 8; i++)
#pragma unroll
                for (int j = 0; j < 8; j++)
                    acc[i][j] = fmaf(av[i], bv[j], acc[i][j]);
        }
        __syncthreads();
    }

    float* Cb = C + m0 * Hv + n0;
#pragma unroll
    for (int i = 0; i < 8; i++) {
        long r = (long)(ty * 8 + i);
        float4 v0 = {acc[i][0], acc[i][1], acc[i][2], acc[i][3]};
        float4 v1 = {acc[i][4], acc[i][5], acc[i][6], acc[i][7]};
        *(float4*)&Cb[r * Hv + tx * 4] = v0;
        *(float4*)&Cb[r * Hv + 64 + tx * 4] = v1;
    }
}

// ---------------- deterministic per-channel stats ---------------------------
template <int S>
__global__ void colstats_partial() {
    const float* Y = (S == 1) ? g_y1 : g_y2;
    const int c = threadIdx.x;
    const float* p = Y + (size_t)blockIdx.x * 256 * Hv + c;
    float s = 0.f, q = 0.f;
#pragma unroll 8
    for (int r = 0; r < 256; r++) {
        float v = p[(size_t)r * Hv];
        s += v;
        q = fmaf(v, v, q);
    }
    g_psum[blockIdx.x * Hv + c] = s;
    g_psq[blockIdx.x * Hv + c] = q;
}

template <int S>
__global__ void colstats_finalize(const float* __restrict__ gamma,
                                  const float* __restrict__ beta) {
    const int c = threadIdx.x;
    float s = 0.f, q = 0.f;
    for (int i = 0; i < 256; i++) {
        s += g_psum[i * Hv + c];
        q += g_psq[i * Hv + c];
    }
    const float inv = 1.f / (float)NPTS;
    float mean = s * inv;
    float var = q * inv - mean * mean;
    float sc = gamma[c] * rsqrtf(var + 1e-5f);
    if (S == 1) { g_sc1[c] = sc; g_sh1[c] = beta[c] - mean * sc; }
    else        { g_sc2[c] = sc; g_sh2[c] = beta[c] - mean * sc; }
}

// ---------------- BN2 + ReLU + transpose to (B, H, N) -----------------------
__global__ void bn_transpose_out(float* __restrict__ out) {
    __shared__ float t[32][33];
    const int b = blockIdx.z;
    const int h0 = blockIdx.x * 32;
    const int n0 = blockIdx.y * 32;
    const int tx = threadIdx.x;

    float sc = g_sc2[h0 + tx];
    float sh = g_sh2[h0 + tx];
#pragma unroll
    for (int i = threadIdx.y; i < 32; i += 8) {
        float v = g_y2[((size_t)(b * Nv + n0 + i)) * Hv + h0 + tx];
        t[i][tx] = fmaxf(fmaf(v, sc, sh), 0.f);
    }
    __syncthreads();
#pragma unroll
    for (int i = threadIdx.y; i < 32; i += 8) {
        out[((size_t)(b * Hv + h0 + i)) * Nv + n0 + tx] = t[tx][i];
    }
}

// ---------------- launcher ---------------------------------------------------
extern "C" void kernel_launch(void* const* d_in, const int* in_sizes, int n_in,
                              void* d_out, int out_size) {
    const float* unknown      = (const float*)d_in[0];  // (B, N, 3)
    const float* known        = (const float*)d_in[1];  // (B, M, 3)
    const float* unknow_feats = (const float*)d_in[2];  // (B, C1, N)
    const float* known_feats  = (const float*)d_in[3];  // (B, C2, M)
    const float* w1           = (const float*)d_in[4];  // (H, 768)
    const float* g1           = (const float*)d_in[5];
    const float* b1           = (const float*)d_in[6];
    const float* w2           = (const float*)d_in[7];  // (H, H)
    const float* g2           = (const float*)d_in[8];
    const float* b2           = (const float*)d_in[9];
    float* out = (float*)d_out;                         // (B, H, N)

    dim3 tb(32, 8);

    // w1^T: (256 x 768) -> (768 x 256)
    transpose_k<0><<<dim3(CIN / 32, Hv / 32, 1), tb>>>(w1, Hv, CIN, 0, 0, Hv, 0);
    // w2^T: (256 x 256) -> (256 x 256)
    transpose_k<1><<<dim3(Hv / 32, Hv / 32, 1), tb>>>(w2, Hv, Hv, 0, 0, Hv, 0);
    // known_feats (B, C2, M) -> kfT (B, M, C2)
    transpose_k<2><<<dim3(Mv / 32, C2v / 32, Bv), tb>>>(
        known_feats, C2v, Mv, (long)C2v * Mv, (long)Mv * C2v, C2v, 0);
    // unknow_feats (B, C1, N) -> feats[:, 0:256]
    transpose_k<3><<<dim3(Nv / 32, C1v / 32, Bv), tb>>>(
        unknow_feats, C1v, Nv, (long)C1v * Nv, (long)Nv * CIN, CIN, 0);

    // 3-NN + interpolation -> feats[:, 256:768]
    knn_interp_kernel<<<dim3(Bv, Nv / 256), 256>>>(unknown, known);

    // GEMM1: feats @ w1^T -> y1
    sgemm_kernel<1><<<dim3(Hv / 128, NPTS / 128), 256>>>();

    // BN1 stats
    colstats_partial<1><<<256, 256>>>();
    colstats_finalize<1><<<1, 256>>>(g1, b1);

    // GEMM2 with fused BN1+ReLU on input: y2
    sgemm_kernel<2><<<dim3(Hv / 128, NPTS / 128), 256>>>();

    // BN2 stats
    colstats_partial<2><<<256, 256>>>();
    colstats_finalize<2><<<1, 256>>>(g2, b2);

    // BN2 + ReLU + transpose -> out (B, H, N)
    bn_transpose_out<<<dim3(Hv / 32, Nv / 32, Bv), tb>>>(out);
}

// round 4
// speedup vs baseline: 1.7744x; 1.7744x over previous
#include <cuda_runtime.h>

// Problem constants
#define Bv   16
#define Nv   4096
#define Mv   1024
#define C1v  256
#define C2v  512
#define CIN  768
#define Hv   256
#define NPTS (Bv * Nv)     // 65536

// ---------------- scratch (device globals; no cudaMalloc allowed) ----------
static __device__ float g_kfW[(size_t)Bv * Mv * Hv];      // (B, M, H) projected known feats
static __device__ float g_y1[(size_t)NPTS * Hv];
static __device__ float g_y2[(size_t)NPTS * Hv];
static __device__ float g_wT1[CIN * Hv];                  // w1^T (768 x 256)
static __device__ float g_wT2[Hv * Hv];                   // w2^T (256 x 256)
static __device__ int4   g_nni[NPTS];                     // 3-NN indices per point
static __device__ float4 g_nnw[NPTS];                     // 3-NN weights per point
static __device__ float g_psum[256 * Hv];
static __device__ float g_psq[256 * Hv];
static __device__ float g_sc1[Hv], g_sh1[Hv];
static __device__ float g_sc2[Hv], g_sh2[Hv];

// packed f32x2 FMA (Blackwell): d = a*b + d, lanewise on packed pairs
#define FMA_F32X2(d, a, b) \
    asm("fma.rn.f32x2 %0, %1, %2, %0;" : "+l"(d) : "l"(a), "l"(b))
#define PACK_DUP_F32X2(out, f) \
    asm("mov.b64 %0, {%1, %1};" : "=l"(out) : "f"(f))
#define UNPACK_F32X2(lo, hi, v) \
    asm("mov.b64 {%0, %1}, %2;" : "=f"(lo), "=f"(hi) : "l"(v))

// ---------------- small weight transposes ----------------------------------
template <int DST>
__global__ void transpose_k(const float* __restrict__ in, int rows, int cols) {
    float* out = (DST == 0) ? g_wT1 : g_wT2;
    __shared__ float t[32][33];
    int c = blockIdx.x * 32 + threadIdx.x;
    int r0 = blockIdx.y * 32;
#pragma unroll
    for (int i = threadIdx.y; i < 32; i += 8) {
        int r = r0 + i;
        if (r < rows && c < cols) t[i][threadIdx.x] = in[(long)r * cols + c];
    }
    __syncthreads();
    int oc = r0 + threadIdx.x;
    int orow0 = blockIdx.x * 32;
#pragma unroll
    for (int i = threadIdx.y; i < 32; i += 8) {
        int r = orow0 + i;
        if (r < cols && oc < rows) out[(long)r * rows + oc] = t[threadIdx.x][i];
    }
}

// ---------------- 3-NN (indices + normalized weights only) -----------------
__global__ __launch_bounds__(256) void knn_kernel(
    const float* __restrict__ unknown, const float* __restrict__ known) {
    __shared__ float4 kn[Mv];
    const int b = blockIdx.x;
    const int tid = threadIdx.x;

    const float* kb = known + (long)b * Mv * 3;
    for (int m = tid; m < Mv; m += 256) {
        float x = kb[m * 3 + 0], y = kb[m * 3 + 1], z = kb[m * 3 + 2];
        kn[m] = make_float4(x, y, z, x * x + y * y + z * z);
    }
    __syncthreads();

    const int n = blockIdx.y * 256 + tid;
    const float* up = unknown + ((long)b * Nv + n) * 3;
    float ux = up[0], uy = up[1], uz = up[2];
    float un2 = ux * ux + uy * uy + uz * uz;
    float ax = -2.f * ux, ay = -2.f * uy, az = -2.f * uz;

    float d0 = 1e30f, d1 = 1e30f, d2 = 1e30f;
    int i0 = 0, i1 = 0, i2 = 0;
#pragma unroll 4
    for (int m = 0; m < Mv; m++) {
        float4 p = kn[m];
        float d = fmaf(ax, p.x, fmaf(ay, p.y, fmaf(az, p.z, p.w)));
        if (d < d2) {
            if (d < d1) {
                d2 = d1; i2 = i1;
                if (d < d0) { d1 = d0; i1 = i0; d0 = d; i0 = m; }
                else        { d1 = d;  i1 = m; }
            } else { d2 = d; i2 = m; }
        }
    }
    d0 += un2; d1 += un2; d2 += un2;
    float w0 = 1.f / (d0 + 1e-8f);
    float w1 = 1.f / (d1 + 1e-8f);
    float w2 = 1.f / (d2 + 1e-8f);
    float ws = 1.f / (w0 + w1 + w2);
    g_nni[(long)b * Nv + n] = make_int4(i0, i1, i2, 0);
    g_nnw[(long)b * Nv + n] = make_float4(w0 * ws, w1 * ws, w2 * ws, 0.f);
}

// ---------------- SGEMM family: C(128x128 tile) = A * W --------------------
// MODE 0: kfW  = known_feats^T @ w1[:,C1:]^T   (A K-major, per batch, K=512)
// MODE 1: y1   = uf^T @ w1[:,:C1]^T + NN-gather of kfW (A K-major, K=256)
// MODE 2: y2   = relu(bn1(y1)) @ w2^T          (A m-major, K=256, BN fused)
template <int MODE>
__global__ __launch_bounds__(256, 2) void sgemm_kernel(const float* __restrict__ Ain) {
    constexpr int K = (MODE == 0) ? C2v : Hv;
    constexpr int WROW0 = (MODE == 0) ? C1v : 0;
    constexpr int LDA = (MODE == 0) ? Mv : (MODE == 1) ? Nv : Hv;
    constexpr int ASLD = (MODE == 2) ? 132 : 128;

    __shared__ float As[16][ASLD];
    __shared__ float Bs[16][128];
    __shared__ int4 s_idx[(MODE == 1) ? 128 : 1];
    __shared__ float4 s_w[(MODE == 1) ? 128 : 1];

    const int tid = threadIdx.x;
    const int b = (MODE == 2) ? 0 : blockIdx.z;
    const long m0 = (long)blockIdx.y * 128;
    const int n0 = blockIdx.x * 128;

    const float* A;
    float* C;
    if (MODE == 0) {
        A = Ain + (size_t)b * C2v * Mv;
        C = g_kfW + (size_t)b * Mv * Hv;
    } else if (MODE == 1) {
        A = Ain + (size_t)b * C1v * Nv;
        C = g_y1 + (size_t)b * Nv * Hv;
    } else {
        A = g_y1;
        C = g_y2;
    }
    const float* W = (MODE == 2) ? g_wT2 : g_wT1;
    const float* Wb = W + (long)WROW0 * Hv + n0;

    if (MODE == 1 && tid < 128) {
        s_idx[tid] = g_nni[(long)b * Nv + m0 + tid];
        s_w[tid] = g_nnw[(long)b * Nv + m0 + tid];
    }

    const int tx = tid & 15, ty = tid >> 4;
    unsigned long long acc2[4][8];
#pragma unroll
    for (int i = 0; i < 4; i++)
#pragma unroll
        for (int j = 0; j < 8; j++) acc2[i][j] = 0ULL;

    // loader indices
    const int kr = tid >> 5, mc = (tid & 31) * 4;    // K-major A / W loads
    const int arow = tid >> 2, ac4 = tid & 3;        // m-major A loads (MODE 2)

    for (int k0 = 0; k0 < K; k0 += 16) {
        if (MODE == 2) {
#pragma unroll
            for (int h = 0; h < 2; h++) {
                int r = arow + h * 64;
                float4 v = *(const float4*)&A[(m0 + r) * Hv + k0 + ac4 * 4];
                int kg = k0 + ac4 * 4;
                v.x = fmaxf(fmaf(v.x, g_sc1[kg + 0], g_sh1[kg + 0]), 0.f);
                v.y = fmaxf(fmaf(v.y, g_sc1[kg + 1], g_sh1[kg + 1]), 0.f);
                v.z = fmaxf(fmaf(v.z, g_sc1[kg + 2], g_sh1[kg + 2]), 0.f);
                v.w = fmaxf(fmaf(v.w, g_sc1[kg + 3], g_sh1[kg + 3]), 0.f);
                As[ac4 * 4 + 0][r] = v.x;
                As[ac4 * 4 + 1][r] = v.y;
                As[ac4 * 4 + 2][r] = v.z;
                As[ac4 * 4 + 3][r] = v.w;
            }
        } else {
#pragma unroll
            for (int h = 0; h < 2; h++) {
                int r = kr + h * 8;
                *(float4*)&As[r][mc] =
                    *(const float4*)&A[(long)(k0 + r) * LDA + m0 + mc];
            }
        }
#pragma unroll
        for (int h = 0; h < 2; h++) {
            int r = kr + h * 8;
            *(float4*)&Bs[r][mc] = *(const float4*)&Wb[(long)(k0 + r) * Hv + mc];
        }
        __syncthreads();

#pragma unroll
        for (int kk = 0; kk < 16; kk++) {
            ulonglong2 a01 = *(const ulonglong2*)&As[kk][ty * 8];
            ulonglong2 a23 = *(const ulonglong2*)&As[kk][ty * 8 + 4];
            float4 b0 = *(const float4*)&Bs[kk][tx * 4];
            float4 b1 = *(const float4*)&Bs[kk][64 + tx * 4];
            unsigned long long av[4] = {a01.x, a01.y, a23.x, a23.y};
            unsigned long long bv[8];
            PACK_DUP_F32X2(bv[0], b0.x); PACK_DUP_F32X2(bv[1], b0.y);
            PACK_DUP_F32X2(bv[2], b0.z); PACK_DUP_F32X2(bv[3], b0.w);
            PACK_DUP_F32X2(bv[4], b1.x); PACK_DUP_F32X2(bv[5], b1.y);
            PACK_DUP_F32X2(bv[6], b1.z); PACK_DUP_F32X2(bv[7], b1.w);
#pragma unroll
            for (int i = 0; i < 4; i++)
#pragma unroll
                for (int j = 0; j < 8; j++)
                    FMA_F32X2(acc2[i][j], av[i], bv[j]);
        }
        __syncthreads();
    }

    // unpack accumulators: acc[i][j], row pairs (2*i2, 2*i2+1) in lo/hi
    float acc[8][8];
#pragma unroll
    for (int i2 = 0; i2 < 4; i2++)
#pragma unroll
        for (int j = 0; j < 8; j++)
            UNPACK_F32X2(acc[2 * i2][j], acc[2 * i2 + 1][j], acc2[i2][j]);

#pragma unroll
    for (int i = 0; i < 8; i++) {
        int r = ty * 8 + i;
        float4 v0 = {acc[i][0], acc[i][1], acc[i][2], acc[i][3]};
        float4 v1 = {acc[i][4], acc[i][5], acc[i][6], acc[i][7]};
        if (MODE == 1) {
            int4 id = s_idx[r];
            float4 wv = s_w[r];
            const float* kb = g_kfW + (size_t)b * Mv * Hv + n0;
#pragma unroll
            for (int j = 0; j < 3; j++) {
                int idx = (j == 0) ? id.x : (j == 1) ? id.y : id.z;
                float wj = (j == 0) ? wv.x : (j == 1) ? wv.y : wv.z;
                const float* row = kb + (long)idx * Hv;
                float4 f0 = *(const float4*)&row[tx * 4];
                float4 f1 = *(const float4*)&row[64 + tx * 4];
                v0.x = fmaf(wj, f0.x, v0.x); v0.y = fmaf(wj, f0.y, v0.y);
                v0.z = fmaf(wj, f0.z, v0.z); v0.w = fmaf(wj, f0.w, v0.w);
                v1.x = fmaf(wj, f1.x, v1.x); v1.y = fmaf(wj, f1.y, v1.y);
                v1.z = fmaf(wj, f1.z, v1.z); v1.w = fmaf(wj, f1.w, v1.w);
            }
        }
        float* Cb = C + (m0 + r) * Hv + n0;
        *(float4*)&Cb[tx * 4] = v0;
        *(float4*)&Cb[64 + tx * 4] = v1;
    }
}

// ---------------- deterministic per-channel stats ---------------------------
template <int S>
__global__ void colstats_partial() {
    const float* Y = (S == 1) ? g_y1 : g_y2;
    const int c = threadIdx.x;
    const float* p = Y + (size_t)blockIdx.x * 256 * Hv + c;
    float s = 0.f, q = 0.f;
#pragma unroll 8
    for (int r = 0; r < 256; r++) {
        float v = p[(size_t)r * Hv];
        s += v;
        q = fmaf(v, v, q);
    }
    g_psum[blockIdx.x * Hv + c] = s;
    g_psq[blockIdx.x * Hv + c] = q;
}

template <int S>
__global__ void colstats_finalize(const float* __restrict__ gamma,
                                  const float* __restrict__ beta) {
    const int c = threadIdx.x;
    float s = 0.f, q = 0.f;
    for (int i = 0; i < 256; i++) {
        s += g_psum[i * Hv + c];
        q += g_psq[i * Hv + c];
    }
    const float inv = 1.f / (float)NPTS;
    float mean = s * inv;
    float var = q * inv - mean * mean;
    float sc = gamma[c] * rsqrtf(var + 1e-5f);
    if (S == 1) { g_sc1[c] = sc; g_sh1[c] = beta[c] - mean * sc; }
    else        { g_sc2[c] = sc; g_sh2[c] = beta[c] - mean * sc; }
}

// ---------------- BN2 + ReLU + transpose to (B, H, N) -----------------------
__global__ void bn_transpose_out(float* __restrict__ out) {
    __shared__ float t[32][33];
    const int b = blockIdx.z;
    const int h0 = blockIdx.x * 32;
    const int n0 = blockIdx.y * 32;
    const int tx = threadIdx.x;

    float sc = g_sc2[h0 + tx];
    float sh = g_sh2[h0 + tx];
#pragma unroll
    for (int i = threadIdx.y; i < 32; i += 8) {
        float v = g_y2[((size_t)(b * Nv + n0 + i)) * Hv + h0 + tx];
        t[i][tx] = fmaxf(fmaf(v, sc, sh), 0.f);
    }
    __syncthreads();
#pragma unroll
    for (int i = threadIdx.y; i < 32; i += 8) {
        out[((size_t)(b * Hv + h0 + i)) * Nv + n0 + tx] = t[tx][i];
    }
}

// ---------------- launcher ---------------------------------------------------
extern "C" void kernel_launch(void* const* d_in, const int* in_sizes, int n_in,
                              void* d_out, int out_size) {
    const float* unknown      = (const float*)d_in[0];  // (B, N, 3)
    const float* known        = (const float*)d_in[1];  // (B, M, 3)
    const float* unknow_feats = (const float*)d_in[2];  // (B, C1, N)
    const float* known_feats  = (const float*)d_in[3];  // (B, C2, M)
    const float* w1           = (const float*)d_in[4];  // (H, 768)
    const float* g1           = (const float*)d_in[5];
    const float* b1           = (const float*)d_in[6];
    const float* w2           = (const float*)d_in[7];  // (H, H)
    const float* g2           = (const float*)d_in[8];
    const float* b2           = (const float*)d_in[9];
    float* out = (float*)d_out;                         // (B, H, N)

    dim3 tb(32, 8);

    // weight transposes (tiny)
    transpose_k<0><<<dim3(CIN / 32, Hv / 32), tb>>>(w1, Hv, CIN);
    transpose_k<1><<<dim3(Hv / 32, Hv / 32), tb>>>(w2, Hv, Hv);

    // 3-NN indices + weights
    knn_kernel<<<dim3(Bv, Nv / 256), 256>>>(unknown, known);

    // kfW = known_feats^T @ w1[:, C1:]^T   (B, M, H) — only 2.1 GF
    sgemm_kernel<0><<<dim3(Hv / 128, Mv / 128, Bv), 256>>>(known_feats);

    // y1 = uf^T @ w1[:, :C1]^T + gather(kfW)  — fused interpolation epilogue
    sgemm_kernel<1><<<dim3(Hv / 128, Nv / 128, Bv), 256>>>(unknow_feats);

    // BN1 stats
    colstats_partial<1><<<256, 256>>>();
    colstats_finalize<1><<<1, 256>>>(g1, b1);

    // y2 = relu(bn1(y1)) @ w2^T (BN1+ReLU fused into A load)
    sgemm_kernel<2><<<dim3(Hv / 128, NPTS / 128, 1), 256>>>(nullptr);

    // BN2 stats
    colstats_partial<2><<<256, 256>>>();
    colstats_finalize<2><<<1, 256>>>(g2, b2);

    // BN2 + ReLU + transpose -> out (B, H, N)
    bn_transpose_out<<<dim3(Hv / 32, Nv / 32, Bv), tb>>>(out);
}

// round 7
// speedup vs baseline: 2.5358x; 1.4291x over previous
#include <cuda_runtime.h>
#include <cuda_bf16.h>
#include <cstdint>

// Problem constants
#define Bv   16
#define Nv   4096
#define Mv   1024
#define C1v  256
#define C2v  512
#define Hv   256
#define NPTS  (Bv * Nv)    // 65536
#define KFROWS (Bv * Mv)   // 16384

// ---------------- device-global scratch (no cudaMalloc allowed) -------------
static __device__ __nv_bfloat16 g_kf_hi[(size_t)KFROWS * C2v], g_kf_lo[(size_t)KFROWS * C2v];
static __device__ __nv_bfloat16 g_uf_hi[(size_t)NPTS * C1v],   g_uf_lo[(size_t)NPTS * C1v];
static __device__ __nv_bfloat16 g_w1a_hi[Hv * C1v], g_w1a_lo[Hv * C1v];
static __device__ __nv_bfloat16 g_w1b_hi[Hv * C2v], g_w1b_lo[Hv * C2v];
static __device__ __nv_bfloat16 g_w2_hi[Hv * Hv],   g_w2_lo[Hv * Hv];
static __device__ float g_kfW[(size_t)KFROWS * Hv];
static __device__ float g_y1[(size_t)NPTS * Hv];
static __device__ float g_y2[(size_t)NPTS * Hv];
static __device__ int4   g_nni[NPTS];
static __device__ float4 g_nnw[NPTS];
static __device__ float g_psum[256 * Hv], g_psq[256 * Hv];
static __device__ float g_sc1[Hv], g_sh1[Hv], g_sc2[Hv], g_sh2[Hv];

// ---------------- PTX helpers (all baseline sm_80+, no 'a' features) --------
__device__ __forceinline__ uint32_t smem_u32(const void* p) {
    uint32_t a;
    asm("{ .reg .u64 t; cvta.to.shared.u64 t, %1; cvt.u32.u64 %0, t; }" : "=r"(a) : "l"(p));
    return a;
}
__device__ __forceinline__ void cpasync16(uint32_t dst, const void* src) {
    size_t g = __cvta_generic_to_global(src);
    asm volatile("cp.async.cg.shared.global [%0], [%1], 16;" :: "r"(dst), "l"(g));
}
#define CP_COMMIT() asm volatile("cp.async.commit_group;" ::: "memory")
#define CP_WAIT0()  asm volatile("cp.async.wait_group 0;" ::: "memory")

__device__ __forceinline__ void ldsm4(uint32_t* r, uint32_t addr) {
    asm volatile("ldmatrix.sync.aligned.m8n8.x4.shared.b16 {%0,%1,%2,%3}, [%4];"
        : "=r"(r[0]), "=r"(r[1]), "=r"(r[2]), "=r"(r[3]) : "r"(addr));
}
__device__ __forceinline__ void mma16816(float* d, const uint32_t* a, const uint32_t* b) {
    asm volatile(
        "mma.sync.aligned.m16n8k16.row.col.f32.bf16.bf16.f32 "
        "{%0,%1,%2,%3}, {%4,%5,%6,%7}, {%8,%9}, {%0,%1,%2,%3};"
        : "+f"(d[0]), "+f"(d[1]), "+f"(d[2]), "+f"(d[3])
        : "r"(a[0]), "r"(a[1]), "r"(a[2]), "r"(a[3]), "r"(b[0]), "r"(b[1]));
}

// ---------------- bf16 split helpers ----------------------------------------
__device__ __forceinline__ void split_bf16(float v, __nv_bfloat16& h, __nv_bfloat16& l) {
    h = __float2bfloat16(v);
    l = __float2bfloat16(v - __bfloat162float(h));
}
__device__ __forceinline__ uint32_t pack2(__nv_bfloat16 a, __nv_bfloat16 b) {
    __nv_bfloat162 t(a, b);
    return *reinterpret_cast<uint32_t*>(&t);
}

// ---------------- weight split (w is already [N,K] K-major) -----------------
__global__ void conv_w1(const float* __restrict__ w1) {
    int i = blockIdx.x * 256 + threadIdx.x;   // 256*768
    int n = i / 768, k = i % 768;
    __nv_bfloat16 h, l;
    split_bf16(w1[i], h, l);
    if (k < C1v) { g_w1a_hi[n * C1v + k] = h; g_w1a_lo[n * C1v + k] = l; }
    else { g_w1b_hi[n * C2v + k - C1v] = h; g_w1b_lo[n * C2v + k - C1v] = l; }
}
__global__ void conv_w2(const float* __restrict__ w2) {
    int i = blockIdx.x * 256 + threadIdx.x;
    __nv_bfloat16 h, l;
    split_bf16(w2[i], h, l);
    g_w2_hi[i] = h; g_w2_lo[i] = l;
}

// ---------------- transpose + split: (B, C, Nper) -> (B*Nper, C) hi/lo ------
template <int WHICH>   // 0: kf (C=512, Nper=1024)  1: uf (C=256, Nper=4096)
__global__ void conv_transpose(const float* __restrict__ in) {
    constexpr int C = (WHICH == 0) ? C2v : C1v;
    constexpr int Nper = (WHICH == 0) ? Mv : Nv;
    __nv_bfloat16* hi = (WHICH == 0) ? g_kf_hi : g_uf_hi;
    __nv_bfloat16* lo = (WHICH == 0) ? g_kf_lo : g_uf_lo;
    __shared__ float t[32][33];
    const int b = blockIdx.z;
    const int n0 = blockIdx.x * 32, c0 = blockIdx.y * 32;
    const float* ib = in + ((size_t)b * C + c0) * Nper + n0;
#pragma unroll
    for (int i = threadIdx.y; i < 32; i += 8)
        t[i][threadIdx.x] = ib[(size_t)i * Nper + threadIdx.x];
    __syncthreads();
    size_t base = ((size_t)b * Nper + n0) * C + c0 + threadIdx.x;
#pragma unroll
    for (int i = threadIdx.y; i < 32; i += 8) {
        __nv_bfloat16 h, l;
        split_bf16(t[threadIdx.x][i], h, l);
        hi[base + (size_t)i * C] = h;
        lo[base + (size_t)i * C] = l;
    }
}

// ---------------- 3-NN ------------------------------------------------------
__global__ __launch_bounds__(256) void knn_kernel(
    const float* __restrict__ unknown, const float* __restrict__ known) {
    __shared__ float4 kn[Mv];
    const int b = blockIdx.x;
    const int tid = threadIdx.x;
    const float* kb = known + (long)b * Mv * 3;
    for (int m = tid; m < Mv; m += 256) {
        float x = kb[m * 3], y = kb[m * 3 + 1], z = kb[m * 3 + 2];
        kn[m] = make_float4(x, y, z, x * x + y * y + z * z);
    }
    __syncthreads();
    const int n = blockIdx.y * 256 + tid;
    const float* up = unknown + ((long)b * Nv + n) * 3;
    float ux = up[0], uy = up[1], uz = up[2];
    float un2 = ux * ux + uy * uy + uz * uz;
    float ax = -2.f * ux, ay = -2.f * uy, az = -2.f * uz;
    float d0 = 1e30f, d1 = 1e30f, d2 = 1e30f;
    int i0 = 0, i1 = 0, i2 = 0;
#pragma unroll 4
    for (int m = 0; m < Mv; m++) {
        float4 p = kn[m];
        float d = fmaf(ax, p.x, fmaf(ay, p.y, fmaf(az, p.z, p.w)));
        if (d < d2) {
            if (d < d1) {
                d2 = d1; i2 = i1;
                if (d < d0) { d1 = d0; i1 = i0; d0 = d; i0 = m; }
                else        { d1 = d;  i1 = m; }
            } else { d2 = d; i2 = m; }
        }
    }
    d0 += un2; d1 += un2; d2 += un2;
    float w0 = 1.f / (d0 + 1e-8f), w1 = 1.f / (d1 + 1e-8f), w2 = 1.f / (d2 + 1e-8f);
    float ws = 1.f / (w0 + w1 + w2);
    g_nni[(long)b * Nv + n] = make_int4(i0, i1, i2, 0);
    g_nnw[(long)b * Nv + n] = make_float4(w0 * ws, w1 * ws, w2 * ws, 0.f);
}

// ---------------- HMMA bf16x3 GEMM: CTA tile 128x128, BK=64 ------------------
// MODE 0: kfW = kf @ w1b^T   (K=512)
// MODE 1: y1  = uf @ w1a^T + NN-gather epilogue (K=256)
// MODE 2: y2  = bn_relu(y1) @ w2^T, BN fused into A loader (K=256)
// SMEM layout (dynamic): A_HI 0..16K, A_LO 16K..32K, B_HI 32K..48K, B_LO 48K..64K,
//                        [MODE2] s_sc @64K (1KB), s_sh @65K (1KB)
template <int MODE>
__global__ __launch_bounds__(256, 2) void mma_gemm() {
    constexpr int KTOT = (MODE == 0) ? C2v : Hv;
    constexpr int NCH = KTOT / 64;
    constexpr uint32_t A_HI = 0, A_LO = 16384, B_HI = 32768, B_LO = 49152;

    extern __shared__ char smem[];
    const uint32_t sb = smem_u32(smem);

    const __nv_bfloat16* Ahi = (MODE == 0) ? g_kf_hi : g_uf_hi;
    const __nv_bfloat16* Alo = (MODE == 0) ? g_kf_lo : g_uf_lo;
    const __nv_bfloat16* Bhi = (MODE == 0) ? g_w1b_hi : (MODE == 1) ? g_w1a_hi : g_w2_hi;
    const __nv_bfloat16* Blo = (MODE == 0) ? g_w1b_lo : (MODE == 1) ? g_w1a_lo : g_w2_lo;
    float* Cout = (MODE == 0) ? g_kfW : (MODE == 1) ? g_y1 : g_y2;

    const int tid = threadIdx.x;
    const int lane = tid & 31, wid = tid >> 5;
    const int wr = wid & 3, wc = wid >> 2;        // warp grid 4(m) x 2(n)
    const long m0 = (long)blockIdx.x * 128;
    const int n0g = blockIdx.y * 128;

    float* s_sc = (float*)(smem + 65536);
    float* s_sh = (float*)(smem + 65536 + 1024);
    if (MODE == 2) {
        if (tid < 64) {
            ((float4*)s_sc)[tid] = ((const float4*)g_sc1)[tid];
            ((float4*)s_sh)[tid] = ((const float4*)g_sh1)[tid];
        }
        __syncthreads();
    }

    float acc[2][8][4];
#pragma unroll
    for (int i = 0; i < 2; i++)
#pragma unroll
        for (int j = 0; j < 8; j++)
#pragma unroll
            for (int k = 0; k < 4; k++) acc[i][j][k] = 0.f;

    // per-thread ldmatrix address components
    const int a_r = lane & 15;              // A: row within 16-row tile
    const int a_co = lane >> 4;             // A: chunk offset (0/1)
    const int b_r = (lane & 7) + ((lane >> 4) << 3);  // B: row within n16 group
    const int b_co = (lane >> 3) & 1;       // B: chunk offset

#pragma unroll 1
    for (int kc = 0; kc < NCH; kc++) {
        const int k0 = kc * 64;
        // ---- stage A ----
        if (MODE != 2) {
#pragma unroll
            for (int p = 0; p < 4; p++) {
                int idx = p * 256 + tid;
                int r = idx >> 3, c = idx & 7;
                uint32_t sw = r * 128 + (((uint32_t)(c ^ (r & 7))) << 4);
                const size_t gi = (m0 + r) * (size_t)KTOT + k0 + c * 8;
                cpasync16(sb + A_HI + sw, Ahi + gi);
                cpasync16(sb + A_LO + sw, Alo + gi);
            }
        } else {
#pragma unroll
            for (int p = 0; p < 4; p++) {
                int idx = p * 256 + tid;
                int r = idx >> 3, c = idx & 7;
                int kb = k0 + c * 8;
                const float* src = g_y1 + (m0 + r) * (size_t)Hv + kb;
                float4 x0 = *(const float4*)src;
                float4 x1 = *(const float4*)(src + 4);
                float v[8];
                v[0] = fmaxf(fmaf(x0.x, s_sc[kb + 0], s_sh[kb + 0]), 0.f);
                v[1] = fmaxf(fmaf(x0.y, s_sc[kb + 1], s_sh[kb + 1]), 0.f);
                v[2] = fmaxf(fmaf(x0.z, s_sc[kb + 2], s_sh[kb + 2]), 0.f);
                v[3] = fmaxf(fmaf(x0.w, s_sc[kb + 3], s_sh[kb + 3]), 0.f);
                v[4] = fmaxf(fmaf(x1.x, s_sc[kb + 4], s_sh[kb + 4]), 0.f);
                v[5] = fmaxf(fmaf(x1.y, s_sc[kb + 5], s_sh[kb + 5]), 0.f);
                v[6] = fmaxf(fmaf(x1.z, s_sc[kb + 6], s_sh[kb + 6]), 0.f);
                v[7] = fmaxf(fmaf(x1.w, s_sc[kb + 7], s_sh[kb + 7]), 0.f);
                uint4 hq, lq;
                uint32_t* hp = (uint32_t*)&hq;
                uint32_t* lp = (uint32_t*)&lq;
#pragma unroll
                for (int j = 0; j < 4; j++) {
                    __nv_bfloat16 h0, l0, h1, l1;
                    split_bf16(v[2 * j], h0, l0);
                    split_bf16(v[2 * j + 1], h1, l1);
                    hp[j] = pack2(h0, h1);
                    lp[j] = pack2(l0, l1);
                }
                uint32_t sw = r * 128 + (((uint32_t)(c ^ (r & 7))) << 4);
                *(uint4*)(smem + A_HI + sw) = hq;
                *(uint4*)(smem + A_LO + sw) = lq;
            }
        }
        // ---- stage B ----
#pragma unroll
        for (int p = 0; p < 4; p++) {
            int idx = p * 256 + tid;
            int r = idx >> 3, c = idx & 7;
            uint32_t sw = r * 128 + (((uint32_t)(c ^ (r & 7))) << 4);
            const size_t gi = (size_t)(n0g + r) * KTOT + k0 + c * 8;
            cpasync16(sb + B_HI + sw, Bhi + gi);
            cpasync16(sb + B_LO + sw, Blo + gi);
        }
        CP_COMMIT();
        CP_WAIT0();
        __syncthreads();

        // ---- compute 4 k16 steps ----
#pragma unroll 1
        for (int kk = 0; kk < 4; kk++) {
            uint32_t ah[2][4], al[2][4];
#pragma unroll
            for (int mt = 0; mt < 2; mt++) {
                int row = wr * 32 + mt * 16 + a_r;
                uint32_t ac = (uint32_t)((2 * kk + a_co) ^ (row & 7));
                uint32_t ad = sb + A_HI + row * 128 + (ac << 4);
                ldsm4(ah[mt], ad);
                ldsm4(al[mt], ad + (A_LO - A_HI));
            }
#pragma unroll
            for (int nt2 = 0; nt2 < 4; nt2++) {
                int row = wc * 64 + nt2 * 16 + b_r;
                uint32_t bc = (uint32_t)((2 * kk + b_co) ^ (row & 7));
                uint32_t bd = sb + B_HI + row * 128 + (bc << 4);
                uint32_t bh[4], bl[4];
                ldsm4(bh, bd);
                ldsm4(bl, bd + (B_LO - B_HI));
#pragma unroll
                for (int mt = 0; mt < 2; mt++) {
                    mma16816(acc[mt][nt2 * 2 + 0], ah[mt], bh + 0);
                    mma16816(acc[mt][nt2 * 2 + 0], ah[mt], bl + 0);
                    mma16816(acc[mt][nt2 * 2 + 0], al[mt], bh + 0);
                    mma16816(acc[mt][nt2 * 2 + 1], ah[mt], bh + 2);
                    mma16816(acc[mt][nt2 * 2 + 1], ah[mt], bl + 2);
                    mma16816(acc[mt][nt2 * 2 + 1], al[mt], bh + 2);
                }
            }
        }
        __syncthreads();
    }

    // ---- epilogue ----
    int4* sidx = (int4*)smem;             // reuse A region (post-sync)
    float4* swt = (float4*)(smem + 2048);
    int bIdx = 0;
    if (MODE == 1) {
        bIdx = (int)(m0 >> 12);           // 4096 rows per batch
        if (tid < 128) {
            sidx[tid] = g_nni[m0 + tid];
            swt[tid] = g_nnw[m0 + tid];
        }
        __syncthreads();
    }
    const float* kfb = g_kfW + (size_t)bIdx * Mv * Hv;
    const int g = lane >> 2, tg = lane & 3;
#pragma unroll
    for (int mt = 0; mt < 2; mt++) {
#pragma unroll
        for (int h = 0; h < 2; h++) {
            int rl = wr * 32 + mt * 16 + h * 8 + g;
            long grow = m0 + rl;
            int4 id;
            float4 w;
            if (MODE == 1) { id = sidx[rl]; w = swt[rl]; }
            float* crow = Cout + grow * Hv + n0g + wc * 64 + tg * 2;
#pragma unroll
            for (int nt = 0; nt < 8; nt++) {
                float2 v = {acc[mt][nt][2 * h], acc[mt][nt][2 * h + 1]};
                if (MODE == 1) {
                    int col = n0g + wc * 64 + nt * 8 + tg * 2;
                    float2 f0 = *(const float2*)(kfb + (size_t)id.x * Hv + col);
                    float2 f1 = *(const float2*)(kfb + (size_t)id.y * Hv + col);
                    float2 f2 = *(const float2*)(kfb + (size_t)id.z * Hv + col);
                    v.x += w.x * f0.x + w.y * f1.x + w.z * f2.x;
                    v.y += w.x * f0.y + w.y * f1.y + w.z * f2.y;
                }
                *(float2*)(crow + nt * 8) = v;
            }
        }
    }
}

// ---------------- deterministic per-channel stats ----------------------------
template <int S>
__global__ void colstats() {
    const float* Y = (S == 1) ? g_y1 : g_y2;
    const int c = threadIdx.x;
    const float* p = Y + (size_t)blockIdx.x * 256 * Hv + c;
    float s = 0.f, q = 0.f;
#pragma unroll 8
    for (int r = 0; r < 256; r++) {
        float v = p[(size_t)r * Hv];
        s += v;
        q = fmaf(v, v, q);
    }
    g_psum[blockIdx.x * Hv + c] = s;
    g_psq[blockIdx.x * Hv + c] = q;
}

template <int S>
__global__ void colstats_finalize(const float* __restrict__ gamma,
                                  const float* __restrict__ beta) {
    const int c = threadIdx.x;
    float s = 0.f, q = 0.f;
    for (int i = 0; i < 256; i++) {
        s += g_psum[i * Hv + c];
        q += g_psq[i * Hv + c];
    }
    const float inv = 1.f / (float)NPTS;
    float mean = s * inv;
    float var = q * inv - mean * mean;
    float sc = gamma[c] * rsqrtf(var + 1e-5f);
    if (S == 1) { g_sc1[c] = sc; g_sh1[c] = beta[c] - mean * sc; }
    else        { g_sc2[c] = sc; g_sh2[c] = beta[c] - mean * sc; }
}

// ---------------- BN2 + ReLU + transpose to (B, H, N) ------------------------
__global__ void bn_transpose_out(float* __restrict__ out) {
    __shared__ float t[32][33];
    const int b = blockIdx.z;
    const int h0 = blockIdx.x * 32;
    const int n0 = blockIdx.y * 32;
    const int tx = threadIdx.x;
    float sc = g_sc2[h0 + tx], sh = g_sh2[h0 + tx];
#pragma unroll
    for (int i = threadIdx.y; i < 32; i += 8) {
        float v = g_y2[((size_t)(b * Nv + n0 + i)) * Hv + h0 + tx];
        t[i][tx] = fmaxf(fmaf(v, sc, sh), 0.f);
    }
    __syncthreads();
#pragma unroll
    for (int i = threadIdx.y; i < 32; i += 8)
        out[((size_t)(b * Hv + h0 + i)) * Nv + n0 + tx] = t[tx][i];
}

// ---------------- launcher ----------------------------------------------------
extern "C" void kernel_launch(void* const* d_in, const int* in_sizes, int n_in,
                              void* d_out, int out_size) {
    const float* unknown      = (const float*)d_in[0];
    const float* known        = (const float*)d_in[1];
    const float* unknow_feats = (const float*)d_in[2];
    const float* known_feats  = (const float*)d_in[3];
    const float* w1           = (const float*)d_in[4];
    const float* g1           = (const float*)d_in[5];
    const float* b1           = (const float*)d_in[6];
    const float* w2           = (const float*)d_in[7];
    const float* g2           = (const float*)d_in[8];
    const float* b2           = (const float*)d_in[9];
    float* out = (float*)d_out;

    const int SMEMSZ = 65536 + 2048;   // tiles + BN scale cache
    cudaFuncSetAttribute(mma_gemm<0>, cudaFuncAttributeMaxDynamicSharedMemorySize, SMEMSZ);
    cudaFuncSetAttribute(mma_gemm<1>, cudaFuncAttributeMaxDynamicSharedMemorySize, SMEMSZ);
    cudaFuncSetAttribute(mma_gemm<2>, cudaFuncAttributeMaxDynamicSharedMemorySize, SMEMSZ);

    dim3 tb(32, 8);

    conv_w1<<<768, 256>>>(w1);
    conv_w2<<<256, 256>>>(w2);
    knn_kernel<<<dim3(Bv, Nv / 256), 256>>>(unknown, known);
    conv_transpose<0><<<dim3(Mv / 32, C2v / 32, Bv), tb>>>(known_feats);
    conv_transpose<1><<<dim3(Nv / 32, C1v / 32, Bv), tb>>>(unknow_feats);

    // kfW = kf @ w1b^T  (HMMA bf16x3)
    mma_gemm<0><<<dim3(KFROWS / 128, 2), 256, SMEMSZ>>>();
    // y1 = uf @ w1a^T + NN-gather epilogue
    mma_gemm<1><<<dim3(NPTS / 128, 2), 256, SMEMSZ>>>();

    colstats<1><<<256, 256>>>();
    colstats_finalize<1><<<1, 256>>>(g1, b1);

    // y2 = relu(bn1(y1)) @ w2^T  (BN fused into A loader)
    mma_gemm<2><<<dim3(NPTS / 128, 2), 256, SMEMSZ>>>();

    colstats<2><<<256, 256>>>();
    colstats_finalize<2><<<1, 256>>>(g2, b2);

    bn_transpose_out<<<dim3(Hv / 32, Nv / 32, Bv), tb>>>(out);
}